// round 14
// baseline (speedup 1.0000x reference)
#include <cuda_runtime.h>
#include <cuda_fp16.h>
#include <cstdint>

#define NN   50000
#define NE   600000
#define ETOT 650000          // NE + NN self loops
#define CH   128
#define NL   6
#define NEG  0.2f
#define INVN (1.0f/50000.0f)
#define NBLK_SCAN 196        // ceil(50000/256)
#define GEMM_CTAS 261        // ceil(50000/192)
#define WTOT (NL*128*128)    // 98304
#define NBIN 32              // BN partial bins

// ---------------- scratch (static __device__ arrays, no allocation) ----------------
__device__ float d_bufA[(size_t)NN*CH];   // holds y3 residual
__device__ float d_bufB[(size_t)NN*CH];   // holds y1 residual
__device__ float d_bufG[(size_t)NN*CH];   // pre-BN GAT output of current layer
__device__ __half2 d_hlin[(size_t)NN*64]; // h_lin in fp16 (gather bandwidth x0.5)
__device__ float d_asrc[NN*4];
__device__ float d_adst[NN*4];
__device__ int   d_deg[NN];
__device__ int   d_rowptr[NN+1];
__device__ int   d_colsrc[ETOT];
__device__ int   d_bsums[256];
__device__ float d_bnsum[NL*NBIN*CH];
__device__ float d_bnsq[NL*NBIN*CH];
// W split into tf32 hi/lo, pre-reordered into the GEMM smem image layout
__device__ float d_whi[WTOT];
__device__ float d_wlo[WTOT];

// ---------------- helpers ----------------
__device__ __forceinline__ float leaky(float x) {
    return fmaxf(x, 0.f) + NEG * fminf(x, 0.f);
}
__device__ __forceinline__ uint32_t f2tf32(float x) {
    uint32_t r;
    asm("cvt.rna.tf32.f32 %0, %1;" : "=r"(r) : "f"(x));
    return r;
}
__device__ __forceinline__ void mma8(float* c, uint32_t a0, uint32_t a1,
                                     uint32_t a2, uint32_t a3,
                                     uint32_t b0, uint32_t b1) {
    asm volatile(
        "mma.sync.aligned.m16n8k8.row.col.f32.tf32.tf32.f32 "
        "{%0,%1,%2,%3}, {%4,%5,%6,%7}, {%8,%9}, {%0,%1,%2,%3};"
        : "+f"(c[0]), "+f"(c[1]), "+f"(c[2]), "+f"(c[3])
        : "r"(a0), "r"(a1), "r"(a2), "r"(a3), "r"(b0), "r"(b1));
}

// ---------------- init: zero counters + split/reorder W (once) ----------------
__global__ void k_init(const float* __restrict__ Ws) {
    int i = blockIdx.x * 256 + threadIdx.x;     // grid 384 -> 98304 threads
    if (i < NN) d_deg[i] = 0;
    if (i < NL*NBIN*CH) { d_bnsum[i] = 0.f; d_bnsq[i] = 0.f; }
    if (i == 0) d_rowptr[NN] = ETOT;
    if (i < WTOT) {
        int l = i >> 14, rem = i & 16383;
        int k = rem >> 7, n = rem & 127;
        float v = Ws[i];
        uint32_t hb = f2tf32(v);
        uint32_t lb = f2tf32(v - __uint_as_float(hb));
        int pos = l * 16384 + n * 128 + ((k >> 5) << 5)
                + (((k >> 3) & 3) << 3) + ((k & 3) << 1) + ((k >> 2) & 1);
        d_whi[pos] = __uint_as_float(hb);
        d_wlo[pos] = __uint_as_float(lb);
    }
}

// ---------------- CSR build (by destination) ----------------
__global__ void k_count(const int* __restrict__ ei) {
    int e = blockIdx.x * blockDim.x + threadIdx.x;
    if (e >= ETOT) return;
    int dst = (e < NE) ? ei[NE + e] : (e - NE);
    atomicAdd(&d_deg[dst], 1);
}

__global__ void k_scan_reduce() {
    __shared__ int s[256];
    int i = blockIdx.x * 256 + threadIdx.x;
    s[threadIdx.x] = (i < NN) ? d_deg[i] : 0;
    __syncthreads();
    for (int off = 128; off; off >>= 1) {
        if (threadIdx.x < off) s[threadIdx.x] += s[threadIdx.x + off];
        __syncthreads();
    }
    if (threadIdx.x == 0) d_bsums[blockIdx.x] = s[0];
}

__global__ void k_scan_write() {
    __shared__ int s[256];
    __shared__ int soff[256];
    int tid = threadIdx.x;
    int i = blockIdx.x * 256 + tid;
    int v = (i < NN) ? d_deg[i] : 0;
    soff[tid] = (tid < blockIdx.x) ? d_bsums[tid] : 0;
    s[tid] = v;
    __syncthreads();
    for (int off = 128; off; off >>= 1) {
        if (tid < off) soff[tid] += soff[tid + off];
        __syncthreads();
    }
    for (int off = 1; off < 256; off <<= 1) {
        int t = (tid >= off) ? s[tid - off] : 0;
        __syncthreads();
        s[tid] += t;
        __syncthreads();
    }
    if (i < NN) {
        d_rowptr[i] = soff[0] + s[tid] - v;
        d_deg[i] = 0;
    }
}

__global__ void k_scatter(const int* __restrict__ ei) {
    int e = blockIdx.x * blockDim.x + threadIdx.x;
    if (e >= ETOT) return;
    int src, dst;
    if (e < NE) { src = ei[e]; dst = ei[NE + e]; }
    else        { src = dst = e - NE; }
    int pos = d_rowptr[dst] + atomicAdd(&d_deg[dst], 1);
    d_colsrc[pos] = src;
}

// ---------------- tensor-core GEMM (mma.sync tf32, 3-term), 512 threads ----------------
// CTA tile 192(M) x 128(N); 16 warps 4Mx4N; warp tile 48x32.
// B (full 128x128 hi+lo) staged ONCE, stride-136 rows. A single-buffered per 32-k chunk.
#define GSM_BYTES  202752

__global__ void __launch_bounds__(512, 1)
k_gemm_tc(const float* __restrict__ Ain, const float* __restrict__ Whi,
          const float* __restrict__ Wlo,
          const float* __restrict__ attS, const float* __restrict__ attD,
          const float* __restrict__ bsum, const float* __restrict__ bsq,
          const float* __restrict__ gamma, const float* __restrict__ beta,
          const float* __restrict__ skip, float* __restrict__ writeY) {
    extern __shared__ float smf[];
    float* sAt = smf + 50176;
    float* dAt = smf + 50304;
    float* sc  = smf + 50432;
    float* sh  = smf + 50560;

    int tid = threadIdx.x;
    int lane = tid & 31, g = lane >> 2, t = lane & 3;
    int w = tid >> 5, wm = w >> 2, wn = w & 3;
    int bm = blockIdx.x * 192;

    if (tid < 128) sAt[tid] = attS[tid];
    else if (tid < 256) dAt[tid - 128] = attD[tid - 128];
    else if (bsum != 0 && tid < 384) {
        int c = tid - 256;
        float s1 = 0.f, s2 = 0.f;
#pragma unroll
        for (int b = 0; b < NBIN; b++) {
            s1 += bsum[b * 128 + c];
            s2 += bsq[b * 128 + c];
        }
        float mu  = s1 * INVN;
        float var = s2 * INVN - mu * mu;
        float r = rsqrtf(var + 1e-5f);
        float gg = gamma[c] * r;
        sc[c] = gg;
        sh[c] = beta[c] - gg * mu;
    }

    // ---- stage B (full, once): 8192 float4 (hi then lo) ----
#pragma unroll
    for (int it = 0; it < 16; it++) {
        int f = tid + it * 512;
        int half = f >> 12, ff = f & 4095;
        int n = ff >> 5, j = ff & 31;
        const float4* src4 = (const float4*)(half ? Wlo : Whi);
        float4 v4 = src4[n * 32 + j];
        *(float4*)(smf + 15360 + half * 17408 + n * 136 + j * 4) = v4;
    }

    float cfr[3][4][4];
#pragma unroll
    for (int i = 0; i < 3; i++)
#pragma unroll
        for (int j = 0; j < 4; j++)
#pragma unroll
            for (int q = 0; q < 4; q++) cfr[i][j][q] = 0.f;

    int sRow0 = tid >> 2,        sKs0 = tid & 3;
    int sRow1 = (tid + 512) >> 2, sKs1 = (tid + 512) & 3;
    bool v1 = (tid < 256);
    int gr0 = bm + sRow0, gr1 = bm + sRow1;
    size_t aOff0 = (size_t)gr0 * 128 + sKs0 * 8;
    size_t aOff1 = (size_t)gr1 * 128 + sKs1 * 8;

    float4 aP[2][2], sP[2][2];

    aP[0][0] = aP[0][1] = aP[1][0] = aP[1][1] = make_float4(0.f,0.f,0.f,0.f);
    if (gr0 < NN) {
        aP[0][0] = *(const float4*)(Ain + aOff0);
        aP[0][1] = *(const float4*)(Ain + aOff0 + 4);
        if (skip) { sP[0][0] = *(const float4*)(skip + aOff0);
                    sP[0][1] = *(const float4*)(skip + aOff0 + 4); }
    }
    if (v1 && gr1 < NN) {
        aP[1][0] = *(const float4*)(Ain + aOff1);
        aP[1][1] = *(const float4*)(Ain + aOff1 + 4);
        if (skip) { sP[1][0] = *(const float4*)(skip + aOff1);
                    sP[1][1] = *(const float4*)(skip + aOff1 + 4); }
    }

    // att/sc/sh (and B) must be visible before A-staging READS sc/sh.
    __syncthreads();

    for (int kc = 0; kc < 4; kc++) {
#pragma unroll
        for (int vv = 0; vv < 2; vv++) {
            if (vv == 1 && !v1) break;
            int row = vv ? sRow1 : sRow0;
            int ks  = vv ? sKs1  : sKs0;
            int gr  = vv ? gr1   : gr0;
            float v[8] = {aP[vv][0].x, aP[vv][0].y, aP[vv][0].z, aP[vv][0].w,
                          aP[vv][1].x, aP[vv][1].y, aP[vv][1].z, aP[vv][1].w};
            if (bsum != 0 && gr < NN) {
                int ch = kc*32 + ks*8;
#pragma unroll
                for (int c = 0; c < 8; c++) v[c] = v[c]*sc[ch+c] + sh[ch+c];
                if (skip) {
                    float sv[8] = {sP[vv][0].x, sP[vv][0].y, sP[vv][0].z, sP[vv][0].w,
                                   sP[vv][1].x, sP[vv][1].y, sP[vv][1].z, sP[vv][1].w};
#pragma unroll
                    for (int c = 0; c < 8; c++) v[c] += sv[c];
                }
#pragma unroll
                for (int c = 0; c < 8; c++) v[c] = fmaxf(v[c], 0.f);
                if (writeY) {
                    *(float4*)(writeY + (size_t)gr*128 + kc*32 + ks*8) =
                        make_float4(v[0], v[1], v[2], v[3]);
                    *(float4*)(writeY + (size_t)gr*128 + kc*32 + ks*8 + 4) =
                        make_float4(v[4], v[5], v[6], v[7]);
                }
            }
            float hi[8], lo[8];
#pragma unroll
            for (int c = 0; c < 8; c++) {
                uint32_t hb = f2tf32(v[c]);
                hi[c] = __uint_as_float(hb);
                lo[c] = __uint_as_float(f2tf32(v[c] - __uint_as_float(hb)));
            }
            float* ph = smf + row*40 + ks*8;
            float* pl = ph + 7680;
            *(float4*)(ph)     = make_float4(hi[0], hi[4], hi[1], hi[5]);
            *(float4*)(ph + 4) = make_float4(hi[2], hi[6], hi[3], hi[7]);
            *(float4*)(pl)     = make_float4(lo[0], lo[4], lo[1], lo[5]);
            *(float4*)(pl + 4) = make_float4(lo[2], lo[6], lo[3], lo[7]);
        }
        __syncthreads();

        if (kc < 3) {
            int kn = (kc + 1) * 32;
            aP[0][0] = aP[0][1] = aP[1][0] = aP[1][1] = make_float4(0.f,0.f,0.f,0.f);
            if (gr0 < NN) {
                aP[0][0] = *(const float4*)(Ain + aOff0 + kn);
                aP[0][1] = *(const float4*)(Ain + aOff0 + kn + 4);
                if (skip) { sP[0][0] = *(const float4*)(skip + aOff0 + kn);
                            sP[0][1] = *(const float4*)(skip + aOff0 + kn + 4); }
            }
            if (v1 && gr1 < NN) {
                aP[1][0] = *(const float4*)(Ain + aOff1 + kn);
                aP[1][1] = *(const float4*)(Ain + aOff1 + kn + 4);
                if (skip) { sP[1][0] = *(const float4*)(skip + aOff1 + kn);
                            sP[1][1] = *(const float4*)(skip + aOff1 + kn + 4); }
            }
        }

        float2* A2h = (float2*)smf;
        float2* A2l = (float2*)(smf + 7680);
        float2* B2h = (float2*)(smf + 15360);
        float2* B2l = (float2*)(smf + 32768);
#pragma unroll
        for (int ks = 0; ks < 4; ks++) {
            float2 ah[3][2], al[3][2];
#pragma unroll
            for (int mt = 0; mt < 3; mt++) {
                int r0 = wm*48 + mt*16 + g;
                ah[mt][0] = A2h[r0*20 + ks*4 + t];
                ah[mt][1] = A2h[(r0+8)*20 + ks*4 + t];
                al[mt][0] = A2l[r0*20 + ks*4 + t];
                al[mt][1] = A2l[(r0+8)*20 + ks*4 + t];
            }
#pragma unroll
            for (int nt = 0; nt < 4; nt++) {
                int n = wn*32 + nt*8 + g;
                float2 bh = B2h[n*68 + kc*16 + ks*4 + t];
                float2 bl = B2l[n*68 + kc*16 + ks*4 + t];
                uint32_t bh0 = __float_as_uint(bh.x), bh1 = __float_as_uint(bh.y);
                uint32_t bl0 = __float_as_uint(bl.x), bl1 = __float_as_uint(bl.y);
#pragma unroll
                for (int mt = 0; mt < 3; mt++) {
                    uint32_t a0 = __float_as_uint(ah[mt][0].x);
                    uint32_t a1 = __float_as_uint(ah[mt][1].x);
                    uint32_t a2 = __float_as_uint(ah[mt][0].y);
                    uint32_t a3 = __float_as_uint(ah[mt][1].y);
                    mma8(cfr[mt][nt], a0, a1, a2, a3, bh0, bh1);   // hi*hi
                    mma8(cfr[mt][nt], a0, a1, a2, a3, bl0, bl1);   // hi*lo
                    uint32_t l0 = __float_as_uint(al[mt][0].x);
                    uint32_t l1 = __float_as_uint(al[mt][1].x);
                    uint32_t l2 = __float_as_uint(al[mt][0].y);
                    uint32_t l3 = __float_as_uint(al[mt][1].y);
                    mma8(cfr[mt][nt], l0, l1, l2, l3, bh0, bh1);   // lo*hi
                }
            }
        }
        __syncthreads();
    }

    // ---- epilogue: store h (fp16) + fused per-head alpha dots (head == wn) ----
#pragma unroll
    for (int mt = 0; mt < 3; mt++) {
#pragma unroll
        for (int rr = 0; rr < 2; rr++) {
            int row = bm + wm*48 + mt*16 + rr*8 + g;
            float ps = 0.f, pd = 0.f;
#pragma unroll
            for (int nt = 0; nt < 4; nt++) {
                float c0 = cfr[mt][nt][rr*2 + 0];
                float c1 = cfr[mt][nt][rr*2 + 1];
                int col0 = wn*32 + nt*8 + 2*t;
                if (row < NN)
                    d_hlin[(size_t)row*64 + (col0 >> 1)] = __floats2half2_rn(c0, c1);
                ps += c0 * sAt[col0] + c1 * sAt[col0 + 1];
                pd += c0 * dAt[col0] + c1 * dAt[col0 + 1];
            }
            ps += __shfl_down_sync(0xffffffffu, ps, 2, 4);
            ps += __shfl_down_sync(0xffffffffu, ps, 1, 4);
            pd += __shfl_down_sync(0xffffffffu, pd, 2, 4);
            pd += __shfl_down_sync(0xffffffffu, pd, 1, 4);
            if (t == 0 && row < NN) {
                d_asrc[row*4 + wn] = ps;
                d_adst[row*4 + wn] = pd;
            }
        }
    }
}

// ---------------- GAT aggregation: single-pass online softmax + BN stats ----------------
// latency-bound (ncu probe): cap regs for occupancy; predicated MLP-8 batches (no tail).
__global__ void __launch_bounds__(256, 6)
k_agg(const float* __restrict__ bias_l,
      float* __restrict__ bnsum, float* __restrict__ bnsq) {
    __shared__ int   s_src[8][32];
    __shared__ float s_w[8][128];
    __shared__ float s_p1[8][128];   // per-warp BN sum partials (disjoint writes)
    __shared__ float s_p2[8][128];   // per-warp BN sq partials
    int tid = threadIdx.x;

    int w = tid >> 5, lane = tid & 31;
    int dst = blockIdx.x * 8 + w;
    int beg = d_rowptr[dst], end = d_rowptr[dst + 1];
    int head = lane >> 3;
    float4 ad = *(const float4*)(d_adst + dst * 4);

    float4 m   = make_float4(-1e30f, -1e30f, -1e30f, -1e30f);
    float4 ds  = make_float4(0.f, 0.f, 0.f, 0.f);
    float4 acc = make_float4(0.f, 0.f, 0.f, 0.f);

    for (int base = beg; base < end; base += 32) {
        int idx = base + lane;
        int nE = min(32, end - base);
        int s = 0;
        float4 x = make_float4(-3e38f, -3e38f, -3e38f, -3e38f);
        if (idx < end) {
            s = d_colsrc[idx];
            float4 a = *(const float4*)(d_asrc + s * 4);
            x.x = a.x + ad.x; x.y = a.y + ad.y;
            x.z = a.z + ad.z; x.w = a.w + ad.w;
        }
        // chunk max of raw logits (warp reduce; leaky is monotone)
        float4 c = x;
#pragma unroll
        for (int d = 16; d; d >>= 1) {
            c.x = fmaxf(c.x, __shfl_xor_sync(0xffffffffu, c.x, d));
            c.y = fmaxf(c.y, __shfl_xor_sync(0xffffffffu, c.y, d));
            c.z = fmaxf(c.z, __shfl_xor_sync(0xffffffffu, c.z, d));
            c.w = fmaxf(c.w, __shfl_xor_sync(0xffffffffu, c.w, d));
        }
        float4 lm;
        if (base == beg) {
            // fast path (covers ~all dsts: deg<=32): no running state to rescale
            m = c;
            lm = make_float4(leaky(c.x), leaky(c.y), leaky(c.z), leaky(c.w));
        } else {
            float4 mn = make_float4(fmaxf(m.x, c.x), fmaxf(m.y, c.y),
                                    fmaxf(m.z, c.z), fmaxf(m.w, c.w));
            lm = make_float4(leaky(mn.x), leaky(mn.y), leaky(mn.z), leaky(mn.w));
            float4 f;
            f.x = __expf(leaky(m.x) - lm.x);
            f.y = __expf(leaky(m.y) - lm.y);
            f.z = __expf(leaky(m.z) - lm.z);
            f.w = __expf(leaky(m.w) - lm.w);
            m = mn;
            ds.x *= f.x; ds.y *= f.y; ds.z *= f.z; ds.w *= f.w;
            float fh = (head == 0) ? f.x : (head == 1) ? f.y : (head == 2) ? f.z : f.w;
            acc.x *= fh; acc.y *= fh; acc.z *= fh; acc.w *= fh;
        }

        if (idx < end) {
            float4 wv;
            wv.x = __expf(leaky(x.x) - lm.x);
            wv.y = __expf(leaky(x.y) - lm.y);
            wv.z = __expf(leaky(x.z) - lm.z);
            wv.w = __expf(leaky(x.w) - lm.w);
            ds.x += wv.x; ds.y += wv.y; ds.z += wv.z; ds.w += wv.w;
            s_src[w][lane] = s;
            *(float4*)&s_w[w][lane * 4] = wv;
        }
        __syncwarp();
        // gather: lane owns channels 4*lane..4*lane+3 = 2 half2 = 8B per edge.
        // predicated full batches of 8: lanes past nE alias edge 0 with weight 0
        // (self-loops guarantee deg>=1, so s_src[w][0] is always valid here).
        const __half2* hb = d_hlin + lane * 2;
        int s0 = s_src[w][0];
        for (int j = 0; j < nE; j += 8) {
            int   si[8];
            float wi[8];
            uint2 hv[8];
#pragma unroll
            for (int u = 0; u < 8; u++) {
                int jj = j + u;
                bool ok = jj < nE;
                si[u] = ok ? s_src[w][jj] : s0;
                wi[u] = ok ? s_w[w][jj * 4 + head] : 0.f;
            }
#pragma unroll
            for (int u = 0; u < 8; u++)
                hv[u] = *(const uint2*)(hb + (size_t)si[u] * 64);
#pragma unroll
            for (int u = 0; u < 8; u++) {
                float2 f01 = __half22float2(*(__half2*)&hv[u].x);
                float2 f23 = __half22float2(*(__half2*)&hv[u].y);
                acc.x += f01.x * wi[u]; acc.y += f01.y * wi[u];
                acc.z += f23.x * wi[u]; acc.w += f23.y * wi[u];
            }
        }
        __syncwarp();
    }
#pragma unroll
    for (int d = 16; d; d >>= 1) {
        ds.x += __shfl_xor_sync(0xffffffffu, ds.x, d);
        ds.y += __shfl_xor_sync(0xffffffffu, ds.y, d);
        ds.z += __shfl_xor_sync(0xffffffffu, ds.z, d);
        ds.w += __shfl_xor_sync(0xffffffffu, ds.w, d);
    }
    float dn = (head == 0) ? ds.x : (head == 1) ? ds.y : (head == 2) ? ds.z : ds.w;
    float inv = 1.0f / dn;
    float4 b4 = *(const float4*)(bias_l + lane * 4);
    float4 o = make_float4(acc.x * inv + b4.x, acc.y * inv + b4.y,
                           acc.z * inv + b4.z, acc.w * inv + b4.w);
    *(float4*)(d_bufG + (size_t)dst * 128 + lane * 4) = o;

    // BN partials: disjoint per-(warp,lane) slots -> plain vector stores
    int c0 = lane * 4;
    *(float4*)&s_p1[w][c0] = o;
    *(float4*)&s_p2[w][c0] = make_float4(o.x*o.x, o.y*o.y, o.z*o.z, o.w*o.w);
    __syncthreads();
    if (tid < 128) {
        float s1 = 0.f, s2 = 0.f;
#pragma unroll
        for (int u = 0; u < 8; u++) {
            s1 += s_p1[u][tid];
            s2 += s_p2[u][tid];
        }
        int bin = (blockIdx.x & (NBIN - 1)) * 128;
        atomicAdd(&bnsum[bin + tid], s1);
        atomicAdd(&bnsq[bin + tid],  s2);
    }
}

// ---------------- final BN apply + residual + ReLU (layer 5 only) ----------------
__global__ void k_bn(const float* __restrict__ gamma, const float* __restrict__ beta,
                     const float* __restrict__ bsum,  const float* __restrict__ bsq,
                     const float* __restrict__ skip,  float* __restrict__ out) {
    __shared__ float sc[128], sh[128];
    int tid = threadIdx.x;
    if (tid < 128) {
        float s1 = 0.f, s2 = 0.f;
#pragma unroll
        for (int b = 0; b < NBIN; b++) {
            s1 += bsum[b * 128 + tid];
            s2 += bsq[b * 128 + tid];
        }
        float mu  = s1 * INVN;
        float var = s2 * INVN - mu * mu;
        float r = rsqrtf(var + 1e-5f);
        float gg = gamma[tid] * r;
        sc[tid] = gg;
        sh[tid] = beta[tid] - gg * mu;
    }
    __syncthreads();
    size_t g4 = (size_t)blockIdx.x * 256 + tid;
    int q = (int)(g4 & 31) * 4;
    float4 v = ((const float4*)d_bufG)[g4];
    float4 y;
    y.x = v.x * sc[q+0] + sh[q+0];
    y.y = v.y * sc[q+1] + sh[q+1];
    y.z = v.z * sc[q+2] + sh[q+2];
    y.w = v.w * sc[q+3] + sh[q+3];
    if (skip) {
        float4 s4 = ((const float4*)skip)[g4];
        y.x += s4.x; y.y += s4.y; y.z += s4.z; y.w += s4.w;
    }
    y.x = fmaxf(y.x, 0.f); y.y = fmaxf(y.y, 0.f);
    y.z = fmaxf(y.z, 0.f); y.w = fmaxf(y.w, 0.f);
    ((float4*)out)[g4] = y;
}

// ---------------- launch ----------------
extern "C" void kernel_launch(void* const* d_in, const int* in_sizes, int n_in,
                              void* d_out, int out_size) {
    const float* x       = (const float*)d_in[0];
    const int*   ei      = (const int*)  d_in[1];
    const float* Ws      = (const float*)d_in[2];
    const float* att_src = (const float*)d_in[3];
    const float* att_dst = (const float*)d_in[4];
    const float* biases  = (const float*)d_in[5];
    const float* gammas  = (const float*)d_in[6];
    const float* betas   = (const float*)d_in[7];
    float* out = (float*)d_out;

    void *pA, *pB, *pG, *pSum, *pSq, *pWh, *pWl;
    cudaGetSymbolAddress(&pA, d_bufA);
    cudaGetSymbolAddress(&pB, d_bufB);
    cudaGetSymbolAddress(&pG, d_bufG);
    cudaGetSymbolAddress(&pSum, d_bnsum);
    cudaGetSymbolAddress(&pSq,  d_bnsq);
    cudaGetSymbolAddress(&pWh,  d_whi);
    cudaGetSymbolAddress(&pWl,  d_wlo);
    float* A = (float*)pA;
    float* B = (float*)pB;
    float* G = (float*)pG;
    float* bnsum = (float*)pSum;
    float* bnsq  = (float*)pSq;
    float* whi   = (float*)pWh;
    float* wlo   = (float*)pWl;

    cudaFuncSetAttribute(k_gemm_tc, cudaFuncAttributeMaxDynamicSharedMemorySize, GSM_BYTES);

    // launch index 3 = layer-0 GEMM
    k_init<<<384, 256>>>(Ws);                                    // 0
    k_count<<<(ETOT + 255) / 256, 256>>>(ei);                    // 1
    k_scan_reduce<<<NBLK_SCAN, 256>>>();                         // 2
    k_gemm_tc<<<GEMM_CTAS, 512, GSM_BYTES>>>(x, whi, wlo,        // 3
                                             att_src, att_dst,
                                             0, 0, 0, 0, 0, 0);
    k_scan_write<<<NBLK_SCAN, 256>>>();                          // 4
    k_scatter<<<(ETOT + 255) / 256, 256>>>(ei);                  // 5
    k_agg<<<NN / 8, 256>>>(biases, bnsum, bnsq);                 // 6 (layer 0)

    // layers 1..5: GEMM fuses BN/ReLU/skip of layer l-1
    for (int l = 1; l < NL; l++) {
        const float* skip  = (l == 4) ? B : 0;   // y3 = relu(bn3(G) + y1)
        float*       wrY   = (l == 2) ? B :      // materialize y1
                             (l == 4) ? A : 0;   // materialize y3
        k_gemm_tc<<<GEMM_CTAS, 512, GSM_BYTES>>>(G,
                                                 whi + (size_t)l * 16384,
                                                 wlo + (size_t)l * 16384,
                                                 att_src + l * 128, att_dst + l * 128,
                                                 bnsum + (l - 1) * NBIN * 128,
                                                 bnsq  + (l - 1) * NBIN * 128,
                                                 gammas + (l - 1) * 128, betas + (l - 1) * 128,
                                                 skip, wrY);
        k_agg<<<NN / 8, 256>>>(biases + l * 128,
                               bnsum + l * NBIN * 128, bnsq + l * NBIN * 128);
    }

    // final output: y5 = relu(bn5(G) + y3)
    k_bn<<<NN / 8, 256>>>(gammas + 5 * 128, betas + 5 * 128,
                          bnsum + 5 * NBIN * 128, bnsq + 5 * NBIN * 128, A, out);
}

// round 16
// speedup vs baseline: 1.1795x; 1.1795x over previous
#include <cuda_runtime.h>
#include <cuda_fp16.h>
#include <cuda_bf16.h>
#include <cstdint>

#define NN   50000
#define NE   600000
#define ETOT 650000          // NE + NN self loops
#define CH   128
#define NL   6
#define NEG  0.2f
#define INVN (1.0f/50000.0f)
#define NBLK_SCAN 196        // ceil(50000/256)
#define GEMM_CTAS 261        // ceil(50000/192)
#define NBIN 32              // BN partial bins

// ---------------- scratch (static __device__ arrays, no allocation) ----------------
__device__ float d_bufA[(size_t)NN*CH];   // holds y3 residual
__device__ float d_bufB[(size_t)NN*CH];   // holds y1 residual
__device__ float d_bufG[(size_t)NN*CH];   // pre-BN GAT output of current layer
__device__ __half2 d_hlin[(size_t)NN*64]; // h_lin in fp16 (gather bandwidth x0.5)
__device__ float d_asrc[NN*4];
__device__ float d_adst[NN*4];
__device__ int   d_deg[NN];
__device__ int   d_rowptr[NN+1];
__device__ int   d_colsrc[ETOT];
__device__ int   d_bsums[256];
__device__ float d_bnsum[NL*NBIN*CH];
__device__ float d_bnsq[NL*NBIN*CH];
// W as bf16 hi/lo pairs, pre-packed into the GEMM smem image order:
// per layer: [hi: 128 rows x 64 pair-elts][lo: same] = 16384 uint32
__device__ uint32_t d_wbf[NL*16384];

// ---------------- helpers ----------------
__device__ __forceinline__ float leaky(float x) {
    return fmaxf(x, 0.f) + NEG * fminf(x, 0.f);
}
__device__ __forceinline__ void bf16split(float v, uint16_t& hb, uint16_t& lb, float& hf) {
    __nv_bfloat16 h = __float2bfloat16(v);
    hf = __bfloat162float(h);
    __nv_bfloat16 l = __float2bfloat16(v - hf);
    hb = *(uint16_t*)&h;
    lb = *(uint16_t*)&l;
}
__device__ __forceinline__ void mma16(float* c, uint32_t a0, uint32_t a1,
                                      uint32_t a2, uint32_t a3,
                                      uint32_t b0, uint32_t b1) {
    asm volatile(
        "mma.sync.aligned.m16n8k16.row.col.f32.bf16.bf16.f32 "
        "{%0,%1,%2,%3}, {%4,%5,%6,%7}, {%8,%9}, {%0,%1,%2,%3};"
        : "+f"(c[0]), "+f"(c[1]), "+f"(c[2]), "+f"(c[3])
        : "r"(a0), "r"(a1), "r"(a2), "r"(a3), "r"(b0), "r"(b1));
}

// ---------------- init: zero counters + pack W to bf16 hi/lo image (once) ----------------
__global__ void k_init(const float* __restrict__ Ws) {
    int i = blockIdx.x * 256 + threadIdx.x;     // grid 384 -> 98304 threads
    if (i < NN) d_deg[i] = 0;
    if (i < NL*NBIN*CH) { d_bnsum[i] = 0.f; d_bnsq[i] = 0.f; }
    if (i == 0) d_rowptr[NN] = ETOT;
    if (i < NL * 8192) {                        // (l, kpair j, n)
        int l = i >> 13, rem = i & 8191;
        int j = rem >> 7, n = rem & 127;        // j = k/2 (0..63)
        float w0 = Ws[(size_t)l*16384 + (2*j)   * 128 + n];
        float w1 = Ws[(size_t)l*16384 + (2*j+1) * 128 + n];
        uint16_t h0, l0, h1, l1; float f0, f1;
        bf16split(w0, h0, l0, f0);
        bf16split(w1, h1, l1, f1);
        uint32_t hp = (uint32_t)h0 | ((uint32_t)h1 << 16);
        uint32_t lp = (uint32_t)l0 | ((uint32_t)l1 << 16);
        int i3 = j & 7;
        int elt = ((j >> 3) << 3) + ((i3 & 3) << 1) + (i3 >> 2);  // interleave pos
        d_wbf[(size_t)l*16384 + n*64 + elt]        = hp;
        d_wbf[(size_t)l*16384 + 8192 + n*64 + elt] = lp;
    }
}

// ---------------- CSR build (by destination) ----------------
__global__ void k_count(const int* __restrict__ ei) {
    int e = blockIdx.x * blockDim.x + threadIdx.x;
    if (e >= ETOT) return;
    int dst = (e < NE) ? ei[NE + e] : (e - NE);
    atomicAdd(&d_deg[dst], 1);
}

__global__ void k_scan_reduce() {
    __shared__ int s[256];
    int i = blockIdx.x * 256 + threadIdx.x;
    s[threadIdx.x] = (i < NN) ? d_deg[i] : 0;
    __syncthreads();
    for (int off = 128; off; off >>= 1) {
        if (threadIdx.x < off) s[threadIdx.x] += s[threadIdx.x + off];
        __syncthreads();
    }
    if (threadIdx.x == 0) d_bsums[blockIdx.x] = s[0];
}

__global__ void k_scan_write() {
    __shared__ int s[256];
    __shared__ int soff[256];
    int tid = threadIdx.x;
    int i = blockIdx.x * 256 + tid;
    int v = (i < NN) ? d_deg[i] : 0;
    soff[tid] = (tid < blockIdx.x) ? d_bsums[tid] : 0;
    s[tid] = v;
    __syncthreads();
    for (int off = 128; off; off >>= 1) {
        if (tid < off) soff[tid] += soff[tid + off];
        __syncthreads();
    }
    for (int off = 1; off < 256; off <<= 1) {
        int t = (tid >= off) ? s[tid - off] : 0;
        __syncthreads();
        s[tid] += t;
        __syncthreads();
    }
    if (i < NN) {
        d_rowptr[i] = soff[0] + s[tid] - v;
        d_deg[i] = 0;
    }
}

__global__ void k_scatter(const int* __restrict__ ei) {
    int e = blockIdx.x * blockDim.x + threadIdx.x;
    if (e >= ETOT) return;
    int src, dst;
    if (e < NE) { src = ei[e]; dst = ei[NE + e]; }
    else        { src = dst = e - NE; }
    int pos = d_rowptr[dst] + atomicAdd(&d_deg[dst], 1);
    d_colsrc[pos] = src;
}

// ---------------- tensor-core GEMM (mma.sync bf16 m16n8k16, 3-term), 512 threads ----------
// CTA tile 192(M) x 128(N); 16 warps 4Mx4N; warp tile 48x32.
// Whole A (hi+lo) and B (hi+lo) staged ONCE in smem; 2 syncs total.
// smem uint32 units, row stride 72 elts (elt = bf16x2 pair):
//   Ahi[0,13824) Alo[13824,27648) Bhi[27648,36864) Blo[36864,46080)
//   attS 46080, attD 46208, sc 46336, sh 46464 -> 46592 u32 = 186368 B
#define GSM_BYTES  186368

__global__ void __launch_bounds__(512, 1)
k_gemm_tc(const float* __restrict__ Ain, const uint32_t* __restrict__ Wimg,
          const float* __restrict__ attS, const float* __restrict__ attD,
          const float* __restrict__ bsum, const float* __restrict__ bsq,
          const float* __restrict__ gamma, const float* __restrict__ beta,
          const float* __restrict__ skip, float* __restrict__ writeY) {
    extern __shared__ uint32_t smu[];
    float* sAt = (float*)(smu + 46080);
    float* dAt = (float*)(smu + 46208);
    float* sc  = (float*)(smu + 46336);
    float* sh  = (float*)(smu + 46464);

    int tid = threadIdx.x;
    int lane = tid & 31, g = lane >> 2, t = lane & 3;
    int w = tid >> 5, wm = w >> 2, wn = w & 3;
    int bm = blockIdx.x * 192;

    if (tid < 128) sAt[tid] = attS[tid];
    else if (tid < 256) dAt[tid - 128] = attD[tid - 128];
    else if (bsum != 0 && tid < 384) {
        int c = tid - 256;
        float s1 = 0.f, s2 = 0.f;
#pragma unroll
        for (int b = 0; b < NBIN; b++) {
            s1 += bsum[b * 128 + c];
            s2 += bsq[b * 128 + c];
        }
        float mu  = s1 * INVN;
        float var = s2 * INVN - mu * mu;
        float r = rsqrtf(var + 1e-5f);
        float gg = gamma[c] * r;
        sc[c] = gg;
        sh[c] = beta[c] - gg * mu;
    }

    // ---- stage B (hi+lo, once): 4096 uint4 from packed image ----
#pragma unroll
    for (int it = 0; it < 8; it++) {
        int f = tid + it * 512;                 // 0..4095 uint4
        int half = f >> 11, idx = f & 2047;     // 2048 uint4 per half
        int n = idx >> 4, q = idx & 15;         // 16 uint4 per row
        uint4 v4 = ((const uint4*)Wimg)[f];
        *(uint4*)(smu + 27648 + half * 9216 + n * 72 + q * 4) = v4;
    }
    __syncthreads();   // sc/sh visible before A staging reads them

    // ---- stage A (hi+lo, once): 1536 units of (row, kstep16) ----
#pragma unroll
    for (int it = 0; it < 3; it++) {
        int u = tid + it * 512;
        int row = u >> 3, ks = u & 7;
        int gr = bm + row;
        float v[16];
#pragma unroll
        for (int c = 0; c < 16; c++) v[c] = 0.f;
        if (gr < NN) {
            const float* src = Ain + (size_t)gr * 128 + ks * 16;
#pragma unroll
            for (int q = 0; q < 4; q++) {
                float4 f4 = *(const float4*)(src + q * 4);
                v[q*4+0] = f4.x; v[q*4+1] = f4.y; v[q*4+2] = f4.z; v[q*4+3] = f4.w;
            }
            if (bsum != 0) {
                int ch = ks * 16;
#pragma unroll
                for (int c = 0; c < 16; c++) v[c] = v[c]*sc[ch+c] + sh[ch+c];
                if (skip) {
                    const float* sp = skip + (size_t)gr * 128 + ks * 16;
#pragma unroll
                    for (int q = 0; q < 4; q++) {
                        float4 f4 = *(const float4*)(sp + q * 4);
                        v[q*4+0] += f4.x; v[q*4+1] += f4.y;
                        v[q*4+2] += f4.z; v[q*4+3] += f4.w;
                    }
                }
#pragma unroll
                for (int c = 0; c < 16; c++) v[c] = fmaxf(v[c], 0.f);
                if (writeY) {
                    float* dst = writeY + (size_t)gr * 128 + ks * 16;
#pragma unroll
                    for (int q = 0; q < 4; q++)
                        *(float4*)(dst + q * 4) =
                            make_float4(v[q*4+0], v[q*4+1], v[q*4+2], v[q*4+3]);
                }
            }
        }
        uint32_t hp[8], lp[8];
#pragma unroll
        for (int i = 0; i < 8; i++) {
            uint16_t h0, l0, h1, l1; float f0, f1;
            bf16split(v[2*i],   h0, l0, f0);
            bf16split(v[2*i+1], h1, l1, f1);
            hp[i] = (uint32_t)h0 | ((uint32_t)h1 << 16);
            lp[i] = (uint32_t)l0 | ((uint32_t)l1 << 16);
        }
        // interleave [p0,p4,p1,p5,p2,p6,p3,p7]
        uint32_t* ph = smu + row * 72 + ks * 8;
        uint32_t* pl = ph + 13824;
        *(uint4*)(ph)     = make_uint4(hp[0], hp[4], hp[1], hp[5]);
        *(uint4*)(ph + 4) = make_uint4(hp[2], hp[6], hp[3], hp[7]);
        *(uint4*)(pl)     = make_uint4(lp[0], lp[4], lp[1], lp[5]);
        *(uint4*)(pl + 4) = make_uint4(lp[2], lp[6], lp[3], lp[7]);
    }
    __syncthreads();

    float cfr[3][4][4];
#pragma unroll
    for (int i = 0; i < 3; i++)
#pragma unroll
        for (int j = 0; j < 4; j++)
#pragma unroll
            for (int q = 0; q < 4; q++) cfr[i][j][q] = 0.f;

    // ---- compute: 8 ksteps of 16 ----
#pragma unroll
    for (int ks = 0; ks < 8; ks++) {
        uint2 ah[3][2], al[3][2];
#pragma unroll
        for (int mt = 0; mt < 3; mt++) {
            int r0 = wm*48 + mt*16 + g;
            const uint32_t* pa = smu + r0*72 + ks*8 + 2*t;
            ah[mt][0] = *(const uint2*)(pa);
            ah[mt][1] = *(const uint2*)(pa + 576);          // row +8
            al[mt][0] = *(const uint2*)(pa + 13824);
            al[mt][1] = *(const uint2*)(pa + 13824 + 576);
        }
#pragma unroll
        for (int nt = 0; nt < 4; nt++) {
            int n = wn*32 + nt*8 + g;
            const uint32_t* pb = smu + 27648 + n*72 + ks*8 + 2*t;
            uint2 bh = *(const uint2*)(pb);
            uint2 bl = *(const uint2*)(pb + 9216);
#pragma unroll
            for (int mt = 0; mt < 3; mt++) {
                uint32_t a0 = ah[mt][0].x, a1 = ah[mt][1].x;
                uint32_t a2 = ah[mt][0].y, a3 = ah[mt][1].y;
                mma16(cfr[mt][nt], a0, a1, a2, a3, bh.x, bh.y);   // hi*hi
                mma16(cfr[mt][nt], a0, a1, a2, a3, bl.x, bl.y);   // hi*lo
                uint32_t l0 = al[mt][0].x, l1 = al[mt][1].x;
                uint32_t l2 = al[mt][0].y, l3 = al[mt][1].y;
                mma16(cfr[mt][nt], l0, l1, l2, l3, bh.x, bh.y);   // lo*hi
            }
        }
    }

    // ---- epilogue: store h (fp16) + fused per-head alpha dots (head == wn) ----
#pragma unroll
    for (int mt = 0; mt < 3; mt++) {
#pragma unroll
        for (int rr = 0; rr < 2; rr++) {
            int row = bm + wm*48 + mt*16 + rr*8 + g;
            float ps = 0.f, pd = 0.f;
#pragma unroll
            for (int nt = 0; nt < 4; nt++) {
                float c0 = cfr[mt][nt][rr*2 + 0];
                float c1 = cfr[mt][nt][rr*2 + 1];
                int col0 = wn*32 + nt*8 + 2*t;
                if (row < NN)
                    d_hlin[(size_t)row*64 + (col0 >> 1)] = __floats2half2_rn(c0, c1);
                ps += c0 * sAt[col0] + c1 * sAt[col0 + 1];
                pd += c0 * dAt[col0] + c1 * dAt[col0 + 1];
            }
            ps += __shfl_down_sync(0xffffffffu, ps, 2, 4);
            ps += __shfl_down_sync(0xffffffffu, ps, 1, 4);
            pd += __shfl_down_sync(0xffffffffu, pd, 2, 4);
            pd += __shfl_down_sync(0xffffffffu, pd, 1, 4);
            if (t == 0 && row < NN) {
                d_asrc[row*4 + wn] = ps;
                d_adst[row*4 + wn] = pd;
            }
        }
    }
}

// ---------------- GAT aggregation: single-pass online softmax + BN stats ----------------
// (R13 version: fast-path first chunk, MLP-8 batches + serial tail, no reg cap)
__global__ void k_agg(const float* __restrict__ bias_l,
                      float* __restrict__ bnsum, float* __restrict__ bnsq) {
    __shared__ int   s_src[8][32];
    __shared__ float s_w[8][128];
    __shared__ float s_p1[8][128];
    __shared__ float s_p2[8][128];
    int tid = threadIdx.x;

    int w = tid >> 5, lane = tid & 31;
    int dst = blockIdx.x * 8 + w;
    int beg = d_rowptr[dst], end = d_rowptr[dst + 1];
    int head = lane >> 3;
    float4 ad = *(const float4*)(d_adst + dst * 4);

    float4 m   = make_float4(-1e30f, -1e30f, -1e30f, -1e30f);
    float4 ds  = make_float4(0.f, 0.f, 0.f, 0.f);
    float4 acc = make_float4(0.f, 0.f, 0.f, 0.f);

    for (int base = beg; base < end; base += 32) {
        int idx = base + lane;
        int nE = min(32, end - base);
        int s = 0;
        float4 x = make_float4(-3e38f, -3e38f, -3e38f, -3e38f);
        if (idx < end) {
            s = d_colsrc[idx];
            float4 a = *(const float4*)(d_asrc + s * 4);
            x.x = a.x + ad.x; x.y = a.y + ad.y;
            x.z = a.z + ad.z; x.w = a.w + ad.w;
        }
        float4 c = x;
#pragma unroll
        for (int d = 16; d; d >>= 1) {
            c.x = fmaxf(c.x, __shfl_xor_sync(0xffffffffu, c.x, d));
            c.y = fmaxf(c.y, __shfl_xor_sync(0xffffffffu, c.y, d));
            c.z = fmaxf(c.z, __shfl_xor_sync(0xffffffffu, c.z, d));
            c.w = fmaxf(c.w, __shfl_xor_sync(0xffffffffu, c.w, d));
        }
        float4 lm;
        if (base == beg) {
            m = c;
            lm = make_float4(leaky(c.x), leaky(c.y), leaky(c.z), leaky(c.w));
        } else {
            float4 mn = make_float4(fmaxf(m.x, c.x), fmaxf(m.y, c.y),
                                    fmaxf(m.z, c.z), fmaxf(m.w, c.w));
            lm = make_float4(leaky(mn.x), leaky(mn.y), leaky(mn.z), leaky(mn.w));
            float4 f;
            f.x = __expf(leaky(m.x) - lm.x);
            f.y = __expf(leaky(m.y) - lm.y);
            f.z = __expf(leaky(m.z) - lm.z);
            f.w = __expf(leaky(m.w) - lm.w);
            m = mn;
            ds.x *= f.x; ds.y *= f.y; ds.z *= f.z; ds.w *= f.w;
            float fh = (head == 0) ? f.x : (head == 1) ? f.y : (head == 2) ? f.z : f.w;
            acc.x *= fh; acc.y *= fh; acc.z *= fh; acc.w *= fh;
        }

        if (idx < end) {
            float4 wv;
            wv.x = __expf(leaky(x.x) - lm.x);
            wv.y = __expf(leaky(x.y) - lm.y);
            wv.z = __expf(leaky(x.z) - lm.z);
            wv.w = __expf(leaky(x.w) - lm.w);
            ds.x += wv.x; ds.y += wv.y; ds.z += wv.z; ds.w += wv.w;
            s_src[w][lane] = s;
            *(float4*)&s_w[w][lane * 4] = wv;
        }
        __syncwarp();
        const __half2* hb = d_hlin + lane * 2;
        int j = 0;
        for (; j + 8 <= nE; j += 8) {
            int   si[8];
            float wi[8];
            uint2 hv[8];
#pragma unroll
            for (int u = 0; u < 8; u++) {
                si[u] = s_src[w][j + u];
                wi[u] = s_w[w][(j + u) * 4 + head];
            }
#pragma unroll
            for (int u = 0; u < 8; u++)
                hv[u] = *(const uint2*)(hb + (size_t)si[u] * 64);
#pragma unroll
            for (int u = 0; u < 8; u++) {
                float2 f01 = __half22float2(*(__half2*)&hv[u].x);
                float2 f23 = __half22float2(*(__half2*)&hv[u].y);
                acc.x += f01.x * wi[u]; acc.y += f01.y * wi[u];
                acc.z += f23.x * wi[u]; acc.w += f23.y * wi[u];
            }
        }
        for (; j < nE; j++) {
            int s2 = s_src[w][j];
            float wt = s_w[w][j * 4 + head];
            uint2 hv = *(const uint2*)(hb + (size_t)s2 * 64);
            float2 f01 = __half22float2(*(__half2*)&hv.x);
            float2 f23 = __half22float2(*(__half2*)&hv.y);
            acc.x += f01.x * wt; acc.y += f01.y * wt;
            acc.z += f23.x * wt; acc.w += f23.y * wt;
        }
        __syncwarp();
    }
#pragma unroll
    for (int d = 16; d; d >>= 1) {
        ds.x += __shfl_xor_sync(0xffffffffu, ds.x, d);
        ds.y += __shfl_xor_sync(0xffffffffu, ds.y, d);
        ds.z += __shfl_xor_sync(0xffffffffu, ds.z, d);
        ds.w += __shfl_xor_sync(0xffffffffu, ds.w, d);
    }
    float dn = (head == 0) ? ds.x : (head == 1) ? ds.y : (head == 2) ? ds.z : ds.w;
    float inv = 1.0f / dn;
    float4 b4 = *(const float4*)(bias_l + lane * 4);
    float4 o = make_float4(acc.x * inv + b4.x, acc.y * inv + b4.y,
                           acc.z * inv + b4.z, acc.w * inv + b4.w);
    *(float4*)(d_bufG + (size_t)dst * 128 + lane * 4) = o;

    int c0 = lane * 4;
    *(float4*)&s_p1[w][c0] = o;
    *(float4*)&s_p2[w][c0] = make_float4(o.x*o.x, o.y*o.y, o.z*o.z, o.w*o.w);
    __syncthreads();
    if (tid < 128) {
        float s1 = 0.f, s2 = 0.f;
#pragma unroll
        for (int u = 0; u < 8; u++) {
            s1 += s_p1[u][tid];
            s2 += s_p2[u][tid];
        }
        int bin = (blockIdx.x & (NBIN - 1)) * 128;
        atomicAdd(&bnsum[bin + tid], s1);
        atomicAdd(&bnsq[bin + tid],  s2);
    }
}

// ---------------- final BN apply + residual + ReLU (layer 5 only) ----------------
__global__ void k_bn(const float* __restrict__ gamma, const float* __restrict__ beta,
                     const float* __restrict__ bsum,  const float* __restrict__ bsq,
                     const float* __restrict__ skip,  float* __restrict__ out) {
    __shared__ float sc[128], sh[128];
    int tid = threadIdx.x;
    if (tid < 128) {
        float s1 = 0.f, s2 = 0.f;
#pragma unroll
        for (int b = 0; b < NBIN; b++) {
            s1 += bsum[b * 128 + tid];
            s2 += bsq[b * 128 + tid];
        }
        float mu  = s1 * INVN;
        float var = s2 * INVN - mu * mu;
        float r = rsqrtf(var + 1e-5f);
        float gg = gamma[tid] * r;
        sc[tid] = gg;
        sh[tid] = beta[tid] - gg * mu;
    }
    __syncthreads();
    size_t g4 = (size_t)blockIdx.x * 256 + tid;
    int q = (int)(g4 & 31) * 4;
    float4 v = ((const float4*)d_bufG)[g4];
    float4 y;
    y.x = v.x * sc[q+0] + sh[q+0];
    y.y = v.y * sc[q+1] + sh[q+1];
    y.z = v.z * sc[q+2] + sh[q+2];
    y.w = v.w * sc[q+3] + sh[q+3];
    if (skip) {
        float4 s4 = ((const float4*)skip)[g4];
        y.x += s4.x; y.y += s4.y; y.z += s4.z; y.w += s4.w;
    }
    y.x = fmaxf(y.x, 0.f); y.y = fmaxf(y.y, 0.f);
    y.z = fmaxf(y.z, 0.f); y.w = fmaxf(y.w, 0.f);
    ((float4*)out)[g4] = y;
}

// ---------------- launch ----------------
extern "C" void kernel_launch(void* const* d_in, const int* in_sizes, int n_in,
                              void* d_out, int out_size) {
    const float* x       = (const float*)d_in[0];
    const int*   ei      = (const int*)  d_in[1];
    const float* Ws      = (const float*)d_in[2];
    const float* att_src = (const float*)d_in[3];
    const float* att_dst = (const float*)d_in[4];
    const float* biases  = (const float*)d_in[5];
    const float* gammas  = (const float*)d_in[6];
    const float* betas   = (const float*)d_in[7];
    float* out = (float*)d_out;

    void *pA, *pB, *pG, *pSum, *pSq, *pW;
    cudaGetSymbolAddress(&pA, d_bufA);
    cudaGetSymbolAddress(&pB, d_bufB);
    cudaGetSymbolAddress(&pG, d_bufG);
    cudaGetSymbolAddress(&pSum, d_bnsum);
    cudaGetSymbolAddress(&pSq,  d_bnsq);
    cudaGetSymbolAddress(&pW,   d_wbf);
    float* A = (float*)pA;
    float* B = (float*)pB;
    float* G = (float*)pG;
    float* bnsum = (float*)pSum;
    float* bnsq  = (float*)pSq;
    uint32_t* wimg = (uint32_t*)pW;

    cudaFuncSetAttribute(k_gemm_tc, cudaFuncAttributeMaxDynamicSharedMemorySize, GSM_BYTES);

    // launch index 3 = layer-0 GEMM (profiled by ncu)
    k_init<<<384, 256>>>(Ws);                                    // 0
    k_count<<<(ETOT + 255) / 256, 256>>>(ei);                    // 1
    k_scan_reduce<<<NBLK_SCAN, 256>>>();                         // 2
    k_gemm_tc<<<GEMM_CTAS, 512, GSM_BYTES>>>(x, wimg,            // 3
                                             att_src, att_dst,
                                             0, 0, 0, 0, 0, 0);
    k_scan_write<<<NBLK_SCAN, 256>>>();                          // 4
    k_scatter<<<(ETOT + 255) / 256, 256>>>(ei);                  // 5
    k_agg<<<NN / 8, 256>>>(biases, bnsum, bnsq);                 // 6 (layer 0)

    // layers 1..5: GEMM fuses BN/ReLU/skip of layer l-1
    for (int l = 1; l < NL; l++) {
        const float* skip  = (l == 4) ? B : 0;   // y3 = relu(bn3(G) + y1)
        float*       wrY   = (l == 2) ? B :      // materialize y1
                             (l == 4) ? A : 0;   // materialize y3
        k_gemm_tc<<<GEMM_CTAS, 512, GSM_BYTES>>>(G,
                                                 wimg + (size_t)l * 16384,
                                                 att_src + l * 128, att_dst + l * 128,
                                                 bnsum + (l - 1) * NBIN * 128,
                                                 bnsq  + (l - 1) * NBIN * 128,
                                                 gammas + (l - 1) * 128, betas + (l - 1) * 128,
                                                 skip, wrY);
        k_agg<<<NN / 8, 256>>>(biases + l * 128,
                               bnsum + l * NBIN * 128, bnsq + l * NBIN * 128);
    }

    // final output: y5 = relu(bn5(G) + y3)
    k_bn<<<NN / 8, 256>>>(gammas + 5 * 128, betas + 5 * 128,
                          bnsum + 5 * NBIN * 128, bnsq + 5 * NBIN * 128, A, out);
}